// round 2
// baseline (speedup 1.0000x reference)
#include <cuda_runtime.h>
#include <cstdint>

// ---------------------------------------------------------------------------
// StaticDualExpertLinear: out[t,:] = x[t,:] @ W_sel(t)^T + b_sel(t)
// Token-partitioned (1 GEMM per token) + mma.sync tf32 (portable sm_80+ path;
// tcgen05 is unavailable: harness compiles for plain sm_100).
// ---------------------------------------------------------------------------

#define TOKENS   8192
#define KDIM     2048
#define NDIM     2048
#define BM       128
#define BN       256
#define BK       32
#define NCHUNKS  (KDIM / BK)      // 64
#define STAGES   3
#define RS       36               // padded row stride (floats): conflict-free LDS
#define A_STG    (BM * RS)        // 4608 floats
#define B_STG    (BN * RS)        // 9216 floats
#define STG      (A_STG + B_STG)  // 13824 floats
#define DYN_BYTES (STAGES * STG * 4)   // 165888 B

__device__ int g_perm[TOKENS];
__device__ int g_ntext;

// ---------------- helpers ----------------
__device__ __forceinline__ uint32_t f2tf(float f) {
    uint32_t r;
    asm("cvt.rna.tf32.f32 %0, %1;" : "=r"(r) : "f"(f));
    return r;
}
__device__ __forceinline__ void cp16(void* smem_ptr, const void* gptr) {
    uint32_t s = (uint32_t)__cvta_generic_to_shared(smem_ptr);
    asm volatile("cp.async.cg.shared.global [%0], [%1], 16;" :: "r"(s), "l"(gptr));
}
__device__ __forceinline__ void cp_commit() {
    asm volatile("cp.async.commit_group;" ::: "memory");
}
template <int N>
__device__ __forceinline__ void cp_wait() {
    asm volatile("cp.async.wait_group %0;" :: "n"(N) : "memory");
}
__device__ __forceinline__ void mma_tf32(float* c, uint32_t a0, uint32_t a1,
                                         uint32_t a2, uint32_t a3,
                                         uint32_t b0, uint32_t b1) {
    asm volatile(
        "mma.sync.aligned.m16n8k8.row.col.f32.tf32.tf32.f32 "
        "{%0,%1,%2,%3}, {%4,%5,%6,%7}, {%8,%9}, {%0,%1,%2,%3};"
        : "+f"(c[0]), "+f"(c[1]), "+f"(c[2]), "+f"(c[3])
        : "r"(a0), "r"(a1), "r"(a2), "r"(a3), "r"(b0), "r"(b1));
}

// ---------------------------------------------------------------------------
// Kernel 1: stable partition of tokens: text (mod==0) first, then image.
// ---------------------------------------------------------------------------
__global__ void partition_kernel(const int* __restrict__ mod) {
    __shared__ int s[256];
    const int t = threadIdx.x;
    const int base = t * 32;
    int c = 0;
#pragma unroll
    for (int i = 0; i < 32; i++) c += (mod[base + i] == 0);
    s[t] = c;
    __syncthreads();
    for (int off = 1; off < 256; off <<= 1) {
        int v = (t >= off) ? s[t - off] : 0;
        __syncthreads();
        s[t] += v;
        __syncthreads();
    }
    const int incl = s[t];
    const int total = s[255];
    int text_pos = incl - c;
    int img_pos = total + (base - text_pos);
#pragma unroll 4
    for (int i = 0; i < 32; i++) {
        int tok = base + i;
        if (mod[tok] == 0) g_perm[text_pos++] = tok;
        else               g_perm[img_pos++]  = tok;
    }
    if (t == 0) g_ntext = total;
}

// ---------------------------------------------------------------------------
// Kernel 2: tf32 mma.sync GEMM. CTA tile 128x256, BK=32, 3-stage cp.async.
// 8 warps, each 64x64 (4 m-frags x 8 n-frags of m16n8k8).
// ---------------------------------------------------------------------------
__global__ void __launch_bounds__(256, 1)
dual_gemm_kernel(const float* __restrict__ x,
                 const float* __restrict__ Wimg, const float* __restrict__ bimg,
                 const float* __restrict__ Wtxt, const float* __restrict__ btxt,
                 float* __restrict__ out) {
    extern __shared__ float sm[];
    __shared__ float bias_s[BN];
    __shared__ int rows_s[BM];

    const int ntile = blockIdx.x;   // 0..7
    const int mtile = blockIdx.y;   // 0..64

    const int n_text = g_ntext;
    const int T_text = (n_text + BM - 1) >> 7;
    const int n_img = TOKENS - n_text;
    const int T_img = (n_img + BM - 1) >> 7;
    if (mtile >= T_text + T_img) return;

    const bool is_text = (mtile < T_text);
    const int row_base = is_text ? (mtile * BM) : (n_text + (mtile - T_text) * BM);
    const int group_end = is_text ? n_text : TOKENS;
    const float* W    = is_text ? Wtxt : Wimg;
    const float* bias = is_text ? btxt : bimg;

    const int tid = threadIdx.x;
    const int wid = tid >> 5;
    const int lane = tid & 31;
    const int g = lane >> 2;        // groupID 0..7
    const int t4 = lane & 3;        // threadID in group 0..3
    const int warpM = wid >> 2;     // 0..1
    const int warpN = wid & 3;      // 0..3

    bias_s[tid] = bias[ntile * BN + tid];
    if (tid < BM) {
        int p = row_base + tid;
        int pc = (p < group_end) ? p : (group_end - 1);
        rows_s[tid] = g_perm[pc];
    }
    __syncthreads();

    // ---- load plan: A 128 rows x 8 f4, B 256 rows x 8 f4, 256 threads ----
    const int r0 = tid >> 3;        // 0..31
    const int c4 = tid & 7;         // 0..7 (float4 column)
    const float* aptr[4];
#pragma unroll
    for (int i = 0; i < 4; i++)
        aptr[i] = x + (size_t)rows_s[r0 + 32 * i] * KDIM + c4 * 4;
    const float* bptr[8];
#pragma unroll
    for (int i = 0; i < 8; i++)
        bptr[i] = W + (size_t)(ntile * BN + r0 + 32 * i) * KDIM + c4 * 4;

    auto prefetch = [&](int kc) {
        float* dA = sm + (kc % STAGES) * STG;
        float* dB = dA + A_STG;
        const int koff = kc * BK;
#pragma unroll
        for (int i = 0; i < 4; i++)
            cp16(dA + (r0 + 32 * i) * RS + c4 * 4, aptr[i] + koff);
#pragma unroll
        for (int i = 0; i < 8; i++)
            cp16(dB + (r0 + 32 * i) * RS + c4 * 4, bptr[i] + koff);
        cp_commit();
    };

    float acc[4][8][4];
#pragma unroll
    for (int mf = 0; mf < 4; mf++)
#pragma unroll
        for (int nf = 0; nf < 8; nf++)
#pragma unroll
            for (int i = 0; i < 4; i++) acc[mf][nf][i] = 0.f;

    prefetch(0);
    prefetch(1);

    for (int kc = 0; kc < NCHUNKS; kc++) {
        if (kc + 2 < NCHUNKS) prefetch(kc + 2);
        if (kc + 2 < NCHUNKS)      cp_wait<2>();
        else if (kc + 1 < NCHUNKS) cp_wait<1>();
        else                       cp_wait<0>();
        __syncthreads();

        const float* As = sm + (kc % STAGES) * STG;
        const float* Bs = As + A_STG;
#pragma unroll
        for (int ks = 0; ks < 4; ks++) {
            const int kb = ks * 8;
            uint32_t bf[8][2];
#pragma unroll
            for (int nf = 0; nf < 8; nf++) {
                const int n = warpN * 64 + nf * 8 + g;
                bf[nf][0] = f2tf(Bs[n * RS + kb + t4]);
                bf[nf][1] = f2tf(Bs[n * RS + kb + t4 + 4]);
            }
#pragma unroll
            for (int mf = 0; mf < 4; mf++) {
                const int r = warpM * 64 + mf * 16 + g;
                uint32_t a0 = f2tf(As[r * RS + kb + t4]);
                uint32_t a1 = f2tf(As[(r + 8) * RS + kb + t4]);
                uint32_t a2 = f2tf(As[r * RS + kb + t4 + 4]);
                uint32_t a3 = f2tf(As[(r + 8) * RS + kb + t4 + 4]);
#pragma unroll
                for (int nf = 0; nf < 8; nf++)
                    mma_tf32(acc[mf][nf], a0, a1, a2, a3, bf[nf][0], bf[nf][1]);
            }
        }
        __syncthreads();
    }

    // ---- epilogue: bias + scattered stores (float2, 1 sector per txn) ----
    const int ncol0 = ntile * BN + warpN * 64;
#pragma unroll
    for (int mf = 0; mf < 4; mf++) {
        const int rl0 = warpM * 64 + mf * 16 + g;      // local row (upper half)
#pragma unroll
        for (int half = 0; half < 2; half++) {
            const int rl = rl0 + half * 8;
            const int p = row_base + rl;
            if (p < group_end) {
                const int tok = rows_s[rl];
                float* orow = out + (size_t)tok * NDIM + ncol0 + t4 * 2;
#pragma unroll
                for (int nf = 0; nf < 8; nf++) {
                    float2 v;
                    v.x = acc[mf][nf][half * 2 + 0] + bias_s[warpN * 64 + nf * 8 + t4 * 2];
                    v.y = acc[mf][nf][half * 2 + 1] + bias_s[warpN * 64 + nf * 8 + t4 * 2 + 1];
                    *(float2*)(orow + nf * 8) = v;
                }
            }
        }
    }
}

// ---------------------------------------------------------------------------
extern "C" void kernel_launch(void* const* d_in, const int* in_sizes, int n_in,
                              void* d_out, int out_size) {
    (void)in_sizes; (void)n_in; (void)out_size;
    const float* x    = (const float*)d_in[0];
    const int*   mod  = (const int*)d_in[1];
    const float* Wimg = (const float*)d_in[2];
    const float* bimg = (const float*)d_in[3];
    const float* Wtxt = (const float*)d_in[4];
    const float* btxt = (const float*)d_in[5];
    float* out = (float*)d_out;

    cudaFuncSetAttribute(dual_gemm_kernel,
                         cudaFuncAttributeMaxDynamicSharedMemorySize, DYN_BYTES);

    partition_kernel<<<1, 256>>>(mod);
    dim3 grid(8, 65);
    dual_gemm_kernel<<<grid, 256, DYN_BYTES>>>(x, Wimg, bimg, Wtxt, btxt, out);
}